// round 15
// baseline (speedup 1.0000x reference)
#include <cuda_runtime.h>
#include <math_constants.h>

// TropicalConv2D (max-plus 3x3 depthwise), x:(8,64,224,224) f32, k:(64,1,3,3), s=1,p=1,d=1.
// R15: 8-wide warp-per-row layout (fewest load wavefronts) with register pressure fixed:
//      raw-row rolling + on-demand windows + fused accumulator + launch_bounds(128,10).

#define XB 8
#define XC 64
#define XH 224
#define XW 224
#define LANES 28       // active lanes (28*8 = 224 = full row)
#define RPT 8          // output rows per warp
#define WY 4           // warps per block
#define ROWS_PER_BLOCK (RPT * WY)               // 32
#define STRIPS (XH / ROWS_PER_BLOCK)            // 7

#define NEG_INF (-CUDART_INF_F)

__device__ __forceinline__ float fmax3(float a, float b, float c) {
    float d;
    asm("max.f32 %0, %1, %2, %3;" : "=f"(d) : "f"(a), "f"(b), "f"(c));
    return d;
}

struct Raw { float v[8]; };      // 8 contiguous floats (2 x LDG.128)

__device__ __forceinline__ Raw neg_raw() {
    Raw r;
#pragma unroll
    for (int i = 0; i < 8; i++) r.v[i] = NEG_INF;
    return r;
}

// Load stage: 2 independent LDG.128. No seam scalars (halos = image edges).
template<bool CHECK>
__device__ __forceinline__ Raw load_raw(const float* __restrict__ rowbase, int r) {
    if (CHECK) { if (r < 0 || r >= XH) return neg_raw(); }
    const float* rp = rowbase + r * XW;
    float4 a = *reinterpret_cast<const float4*>(rp);
    float4 b = *reinterpret_cast<const float4*>(rp + 4);
    Raw w;
    w.v[0] = a.x; w.v[1] = a.y; w.v[2] = a.z; w.v[3] = a.w;
    w.v[4] = b.x; w.v[5] = b.y; w.v[6] = b.z; w.v[7] = b.w;
    return w;
}

// Window-row contribution computed on demand from a Raw:
// 2 SHFL + 2 edge SELs + 8 x (3 FADD + 1 FMNMX3).  FIRST: assign; else accumulate.
template<bool FIRST>
__device__ __forceinline__ void contrib(const Raw& r, int lane,
                                        float k0, float k1, float k2, float* a) {
    float wl = __shfl_up_sync(0xffffffffu,   r.v[7], 1);
    float wr = __shfl_down_sync(0xffffffffu, r.v[0], 1);
    if (lane == 0) wl = NEG_INF;
    if (lane >= LANES - 1) wr = NEG_INF;

    float w[10];
    w[0] = wl;
#pragma unroll
    for (int i = 0; i < 8; i++) w[i + 1] = r.v[i];
    w[9] = wr;

#pragma unroll
    for (int j = 0; j < 8; j++) {
        float t = fmax3(w[j] + k0, w[j + 1] + k1, w[j + 2] + k2);
        a[j] = FIRST ? t : fmaxf(a[j], t);
    }
}

template<bool CHECK>
__device__ __forceinline__ void run_strip(
    const float* __restrict__ rowbase, float* __restrict__ orow,
    int row0, int lane, bool active,
    float k00, float k01, float k02,
    float k10, float k11, float k12,
    float k20, float k21, float k22)
{
    // Prologue: three independent row loads (6 LDG.128) in flight.
    Raw rm = load_raw<CHECK>(rowbase, row0 - 1);
    Raw rc = load_raw<CHECK>(rowbase, row0);
    Raw rp = load_raw<CHECK>(rowbase, row0 + 1);

#pragma unroll
    for (int i = 0; i < RPT; i++) {
        const int r = row0 + i;
        // Prefetch row r+2 first; latency covered by this iteration's compute+store.
        Raw rn = load_raw<CHECK>(rowbase, r + 2);

        float a[8];
        contrib<true >(rm, lane, k00, k01, k02, a);
        contrib<false>(rc, lane, k10, k11, k12, a);
        contrib<false>(rp, lane, k20, k21, k22, a);

        if (active) {
            float4 o0, o1;
            o0.x = a[0]; o0.y = a[1]; o0.z = a[2]; o0.w = a[3];
            o1.x = a[4]; o1.y = a[5]; o1.z = a[6]; o1.w = a[7];
            float* dst = orow + r * XW;
            __stwt(reinterpret_cast<float4*>(dst),     o0);
            __stwt(reinterpret_cast<float4*>(dst + 4), o1);
        }
        rm = rc; rc = rp; rp = rn;
    }
}

__global__ __launch_bounds__(128, 10) void tropical_conv3x3_r15(
    const float* __restrict__ x,
    const float* __restrict__ kern,
    float* __restrict__ out)
{
    const int plane = blockIdx.x / STRIPS;             // b*C + c
    const int strip = blockIdx.x % STRIPS;
    const int lane  = threadIdx.x;                      // 0..31
    const int xl    = (lane < LANES) ? lane : (LANES - 1);   // clamp dup lanes
    const bool active = (lane < LANES);
    const int row0  = strip * ROWS_PER_BLOCK + threadIdx.y * RPT;

    const int c = plane & (XC - 1);
    const float* kc = kern + c * 9;
    const float k00 = __ldg(kc + 0), k01 = __ldg(kc + 1), k02 = __ldg(kc + 2);
    const float k10 = __ldg(kc + 3), k11 = __ldg(kc + 4), k12 = __ldg(kc + 5);
    const float k20 = __ldg(kc + 6), k21 = __ldg(kc + 7), k22 = __ldg(kc + 8);

    const float* rowbase = x   + (size_t)plane * (XH * XW) + xl * 8;
    float*       orow    = out + (size_t)plane * (XH * XW) + xl * 8;

    if (strip == 0 || strip == STRIPS - 1) {
        run_strip<true >(rowbase, orow, row0, lane, active,
                         k00, k01, k02, k10, k11, k12, k20, k21, k22);
    } else {
        run_strip<false>(rowbase, orow, row0, lane, active,
                         k00, k01, k02, k10, k11, k12, k20, k21, k22);
    }
}

extern "C" void kernel_launch(void* const* d_in, const int* in_sizes, int n_in,
                              void* d_out, int out_size)
{
    const float* x = (const float*)d_in[0];
    const float* k = (const float*)d_in[1];
    float* out = (float*)d_out;

    dim3 block(32, WY, 1);                               // 128 threads
    dim3 grid(XB * XC * STRIPS, 1, 1);                   // 512 * 7 = 3584 blocks
    tropical_conv3x3_r15<<<grid, block>>>(x, k, out);
}

// round 16
// speedup vs baseline: 1.0649x; 1.0649x over previous
#include <cuda_runtime.h>
#include <math_constants.h>

// TropicalConv2D (max-plus 3x3 depthwise), x:(8,64,224,224) f32, k:(64,1,3,3), s=1,p=1,d=1.
// R16 = R9 (session best, verified): 4-wide register pipeline, 64-lane coalesced layout,
//      interior/boundary template specialization, fmax3 (FMNMX3), depth-1 prefetch,
//      128-thread blocks, streaming stores.

#define XB 8
#define XC 64
#define XH 224
#define XW 224
#define W4 56          // float4 groups per row
#define RPT 8          // output rows per thread
#define BY 2           // row strips per block
#define ROWS_PER_BLOCK (RPT * BY)               // 16
#define STRIPS (XH / ROWS_PER_BLOCK)            // 14

#define NEG_INF (-CUDART_INF_F)

__device__ __forceinline__ float fmax3(float a, float b, float c) {
    float d;
    asm("max.f32 %0, %1, %2, %3;" : "=f"(d) : "f"(a), "f"(b), "f"(c));
    return d;
}

struct Raw { float v0, v1, v2, v3, l, r; };
struct Win { float w[6]; };   // wl, v0..v3, wr

__device__ __forceinline__ Raw neg_raw() {
    Raw w; w.v0 = w.v1 = w.v2 = w.v3 = w.l = w.r = NEG_INF; return w;
}

// Load stage. CHECK=false (interior strips): no row-range test, no neg_raw path.
template<bool CHECK>
__device__ __forceinline__ Raw load_raw(const float* __restrict__ pp, int r,
                                        int x_eff, bool has_l, bool has_r) {
    if (CHECK) { if (r < 0 || r >= XH) return neg_raw(); }
    const float* rp = pp + r * XW + x_eff * 4;
    float4 v = *reinterpret_cast<const float4*>(rp);
    Raw w;
    w.v0 = v.x; w.v1 = v.y; w.v2 = v.z; w.v3 = v.w;
    w.l = has_l ? __ldg(rp - 1) : NEG_INF;
    w.r = has_r ? __ldg(rp + 4) : NEG_INF;
    return w;
}

// Window stage: 2 SHFL + 2 SEL (+1 loop-invariant edge SEL).
__device__ __forceinline__ Win make_win(const Raw& w, int lane, bool right_edge) {
    Win o;
    o.w[1] = w.v0; o.w[2] = w.v1; o.w[3] = w.v2; o.w[4] = w.v3;
    float wl = __shfl_up_sync(0xffffffffu,   w.v3, 1);
    float wr = __shfl_down_sync(0xffffffffu, w.v0, 1);
    o.w[0] = (lane == 0)  ? w.l : wl;
    o.w[5] = (lane == 31) ? w.r : wr;
    if (right_edge) o.w[5] = NEG_INF;
    return o;
}

// Per-window-row horizontal contribution: 3 FADD + 1 FMNMX3 per output.
__device__ __forceinline__ void row_contrib(const Win& w, float k0, float k1, float k2,
                                            float& r0, float& r1, float& r2, float& r3) {
    r0 = fmax3(w.w[0] + k0, w.w[1] + k1, w.w[2] + k2);
    r1 = fmax3(w.w[1] + k0, w.w[2] + k1, w.w[3] + k2);
    r2 = fmax3(w.w[2] + k0, w.w[3] + k1, w.w[4] + k2);
    r3 = fmax3(w.w[3] + k0, w.w[4] + k1, w.w[5] + k2);
}

template<bool CHECK>
__device__ __forceinline__ void run_strip(
    const float* __restrict__ pp, float* __restrict__ op,
    int row0, int x_eff, int lane, bool active, bool right_edge,
    bool has_l, bool has_r,
    float k00, float k01, float k02,
    float k10, float k11, float k12,
    float k20, float k21, float k22)
{
    // Prologue: three independent loads in flight, then resolve first two windows.
    Raw rm = load_raw<CHECK>(pp, row0 - 1, x_eff, has_l, has_r);
    Raw rc = load_raw<CHECK>(pp, row0,     x_eff, has_l, has_r);
    Raw rp = load_raw<CHECK>(pp, row0 + 1, x_eff, has_l, has_r);
    Win wm = make_win(rm, lane, right_edge);
    Win wc = make_win(rc, lane, right_edge);

#pragma unroll
    for (int i = 0; i < RPT; i++) {
        const int r = row0 + i;
        // Prefetch row r+2 first; latency covered by this iteration's compute+store.
        Raw rn = load_raw<CHECK>(pp, r + 2, x_eff, has_l, has_r);
        // Resolve window for row r+1 (raw loaded last iteration).
        Win wp = make_win(rp, lane, right_edge);

        float t0, t1, t2, t3;    // top window-row contribution
        float m0, m1, m2, m3;    // middle
        float b0, b1, b2, b3;    // bottom
        row_contrib(wm, k00, k01, k02, t0, t1, t2, t3);
        row_contrib(wc, k10, k11, k12, m0, m1, m2, m3);
        row_contrib(wp, k20, k21, k22, b0, b1, b2, b3);

        if (active) {
            float4 o;
            o.x = fmax3(t0, m0, b0);
            o.y = fmax3(t1, m1, b1);
            o.z = fmax3(t2, m2, b2);
            o.w = fmax3(t3, m3, b3);
            __stwt(reinterpret_cast<float4*>(op + r * XW + x_eff * 4), o);
        }
        wm = wc; wc = wp; rp = rn;
    }
}

__global__ __launch_bounds__(128) void tropical_conv3x3_r16(
    const float* __restrict__ x,
    const float* __restrict__ kern,
    float* __restrict__ out)
{
    const int plane = blockIdx.x / STRIPS;             // b*C + c
    const int strip = blockIdx.x % STRIPS;
    const int tx    = threadIdx.x;                      // 0..63
    const int lane  = tx & 31;
    const int x_eff = (tx < W4) ? tx : (W4 - 1);
    const bool active     = (tx < W4);
    const bool right_edge = (x_eff >= W4 - 1);
    const bool has_l = (lane == 0)  && (x_eff > 0);
    const bool has_r = (lane == 31) && (x_eff < W4 - 1);
    const int row0  = strip * ROWS_PER_BLOCK + threadIdx.y * RPT;

    const int c = plane & (XC - 1);
    const float* kc = kern + c * 9;
    const float k00 = __ldg(kc + 0), k01 = __ldg(kc + 1), k02 = __ldg(kc + 2);
    const float k10 = __ldg(kc + 3), k11 = __ldg(kc + 4), k12 = __ldg(kc + 5);
    const float k20 = __ldg(kc + 6), k21 = __ldg(kc + 7), k22 = __ldg(kc + 8);

    const float* pp = x   + (size_t)plane * (XH * XW);
    float*       op = out + (size_t)plane * (XH * XW);

    if (strip == 0 || strip == STRIPS - 1) {
        run_strip<true >(pp, op, row0, x_eff, lane, active, right_edge, has_l, has_r,
                         k00, k01, k02, k10, k11, k12, k20, k21, k22);
    } else {
        run_strip<false>(pp, op, row0, x_eff, lane, active, right_edge, has_l, has_r,
                         k00, k01, k02, k10, k11, k12, k20, k21, k22);
    }
}

extern "C" void kernel_launch(void* const* d_in, const int* in_sizes, int n_in,
                              void* d_out, int out_size)
{
    const float* x = (const float*)d_in[0];
    const float* k = (const float*)d_in[1];
    float* out = (float*)d_out;

    dim3 block(64, BY, 1);                               // 128 threads
    dim3 grid(XB * XC * STRIPS, 1, 1);                   // 512 * 14 = 7168 blocks
    tropical_conv3x3_r16<<<grid, block>>>(x, k, out);
}